// round 9
// baseline (speedup 1.0000x reference)
#include <cuda_runtime.h>
#include <cstdint>
#include <cstring>

#define T_STEPS 2048
#define BATCH   8
#define DIMK    1024
#define NST     64
#define M_ROWS  (T_STEPS * BATCH)
#define NCOL    256

// 16 MB scratch: projections, layout [t*BATCH+b][ k(0:64) | q(64:128) | v(128:192) | alpha(192:256) ]
__device__ __align__(16) float g_proj[(size_t)M_ROWS * NCOL];

union F2U { float2 f2; unsigned long long u; };

__device__ __forceinline__ float2 f2fma(float2 a, float2 b, float2 c) {
    F2U ua, ub, uc, ud; ua.f2 = a; ub.f2 = b; uc.f2 = c;
    asm("fma.rn.f32x2 %0, %1, %2, %3;" : "=l"(ud.u) : "l"(ua.u), "l"(ub.u), "l"(uc.u));
    return ud.f2;
}
__device__ __forceinline__ float2 f2mul(float2 a, float2 b) {
    F2U ua, ub, ud; ua.f2 = a; ub.f2 = b;
    asm("mul.rn.f32x2 %0, %1, %2;" : "=l"(ud.u) : "l"(ua.u), "l"(ub.u));
    return ud.f2;
}
__device__ __forceinline__ float2 f2add(float2 a, float2 b) {
    F2U ua, ub, ud; ua.f2 = a; ub.f2 = b;
    asm("add.rn.f32x2 %0, %1, %2;" : "=l"(ud.u) : "l"(ua.u), "l"(ub.u));
    return ud.f2;
}
__device__ __forceinline__ float2 f2dup(float a) {
    F2U ud;
    asm("mov.b64 %0, {%1, %1};" : "=l"(ud.u) : "f"(a));
    return ud.f2;
}
__device__ __forceinline__ float sigmoidf_fast(float x) {
    return __fdividef(1.0f, 1.0f + __expf(-x));
}

// ============================================================================
// tf32 helpers
// ============================================================================
__device__ __forceinline__ uint32_t f2tf(float a) {
    uint32_t r;
    asm("cvt.rna.tf32.f32 %0, %1;" : "=r"(r) : "f"(a));
    return r;
}
__device__ __forceinline__ void tf_split(float a, uint32_t& hi, uint32_t& lo) {
    hi = f2tf(a);
    lo = f2tf(__fsub_rn(a, __uint_as_float(hi)));
}
__device__ __forceinline__ void mma_tf32(float (&d)[4], const uint32_t (&a)[4],
                                         const uint32_t (&b)[2]) {
    asm("mma.sync.aligned.m16n8k8.row.col.f32.tf32.tf32.f32 "
        "{%0,%1,%2,%3},{%4,%5,%6,%7},{%8,%9},{%0,%1,%2,%3};"
        : "+f"(d[0]), "+f"(d[1]), "+f"(d[2]), "+f"(d[3])
        : "r"(a[0]), "r"(a[1]), "r"(a[2]), "r"(a[3]), "r"(b[0]), "r"(b[1]));
}

// ============================================================================
// Kernel 1: projection GEMM on tensor cores, 3xTF32, hi/lo pre-split in smem.
// CTA: 256 thr (8 warps), tile 128m x 64n x 16k. Warp: 32m x 32n.
// Conversion to tf32 hi/lo happens ONCE per element at staging; the inner
// loop is pure LDS.32 -> mma.
// ============================================================================
#define TBM 128
#define TBN 64
#define TBK 16
#define SST 20     // smem k-stride (16 + 4 pad): banks (4g+tg) conflict-free

__global__ void __launch_bounds__(256, 2) proj_tc_kernel(
    const float* __restrict__ x,
    const float* __restrict__ Wk, const float* __restrict__ Wq,
    const float* __restrict__ Wv, const float* __restrict__ Wa,
    const float* __restrict__ b_alpha)
{
    __shared__ __align__(16) uint32_t XsH[TBM * SST];
    __shared__ __align__(16) uint32_t XsL[TBM * SST];
    __shared__ __align__(16) uint32_t WsH[TBN * SST];
    __shared__ __align__(16) uint32_t WsL[TBN * SST];

    const int tid = threadIdx.x;
    const int m0  = blockIdx.x * TBM;
    const int sel = blockIdx.y;
    const float* W = (sel == 0) ? Wk : (sel == 1) ? Wq : (sel == 2) ? Wv : Wa;

    const int warp  = tid >> 5;
    const int lane  = tid & 31;
    const int g     = lane >> 2;       // group 0..7
    const int tg    = lane & 3;        // thread-in-group 0..3
    const int wm    = warp >> 1;       // 0..3  (32 m-rows each)
    const int wn    = warp & 1;        // 0..1  (32 n-cols each)
    const int am0   = wm * 32 + g;
    const int cn0   = wn * 32 + g;

    // loaders: X 128 rows x 16 cols -> tid>>1 row, (tid&1)*8 col (8 floats)
    //          W  64 rows x 16 cols -> tid>>2 row, (tid&3)*4 col (4 floats)
    const int xrow = tid >> 1;
    const int xcol = (tid & 1) * 8;
    const int wrow = tid >> 2;
    const int wcol = (tid & 3) * 4;

    const float* xp = &x[(size_t)(m0 + xrow) * DIMK + xcol];
    const float* wp = &W[(size_t)wrow * DIMK + wcol];

    float acc[2][4][4];
    #pragma unroll
    for (int mt = 0; mt < 2; mt++)
        #pragma unroll
        for (int nt = 0; nt < 4; nt++)
            #pragma unroll
            for (int j = 0; j < 4; j++) acc[mt][nt][j] = 0.f;

    // register prefetch of first K-tile
    float4 xr[2], wr;
    xr[0] = *reinterpret_cast<const float4*>(xp);
    xr[1] = *reinterpret_cast<const float4*>(xp + 4);
    wr    = *reinterpret_cast<const float4*>(wp);

    for (int k0 = 0; k0 < DIMK; k0 += TBK) {
        // stage: convert to tf32 hi/lo, store vectorized
        {
            uint32_t h[8], l[8];
            tf_split(xr[0].x, h[0], l[0]); tf_split(xr[0].y, h[1], l[1]);
            tf_split(xr[0].z, h[2], l[2]); tf_split(xr[0].w, h[3], l[3]);
            tf_split(xr[1].x, h[4], l[4]); tf_split(xr[1].y, h[5], l[5]);
            tf_split(xr[1].z, h[6], l[6]); tf_split(xr[1].w, h[7], l[7]);
            uint32_t base = xrow * SST + xcol;
            *reinterpret_cast<uint4*>(&XsH[base])     = make_uint4(h[0], h[1], h[2], h[3]);
            *reinterpret_cast<uint4*>(&XsH[base + 4]) = make_uint4(h[4], h[5], h[6], h[7]);
            *reinterpret_cast<uint4*>(&XsL[base])     = make_uint4(l[0], l[1], l[2], l[3]);
            *reinterpret_cast<uint4*>(&XsL[base + 4]) = make_uint4(l[4], l[5], l[6], l[7]);

            uint32_t wh[4], wl[4];
            tf_split(wr.x, wh[0], wl[0]); tf_split(wr.y, wh[1], wl[1]);
            tf_split(wr.z, wh[2], wl[2]); tf_split(wr.w, wh[3], wl[3]);
            uint32_t wbase = wrow * SST + wcol;
            *reinterpret_cast<uint4*>(&WsH[wbase]) = make_uint4(wh[0], wh[1], wh[2], wh[3]);
            *reinterpret_cast<uint4*>(&WsL[wbase]) = make_uint4(wl[0], wl[1], wl[2], wl[3]);
        }
        __syncthreads();

        // prefetch next K-tile
        if (k0 + TBK < DIMK) {
            xr[0] = *reinterpret_cast<const float4*>(xp + k0 + TBK);
            xr[1] = *reinterpret_cast<const float4*>(xp + k0 + TBK + 4);
            wr    = *reinterpret_cast<const float4*>(wp + k0 + TBK);
        }

        #pragma unroll
        for (int ks = 0; ks < TBK / 8; ks++) {
            const int kk = ks * 8;

            uint32_t ah[2][4], al[2][4];
            #pragma unroll
            for (int mt = 0; mt < 2; mt++) {
                const int r0 = (am0 + mt * 16) * SST + kk + tg;
                const int r8 = (am0 + mt * 16 + 8) * SST + kk + tg;
                ah[mt][0] = XsH[r0];     al[mt][0] = XsL[r0];
                ah[mt][1] = XsH[r8];     al[mt][1] = XsL[r8];
                ah[mt][2] = XsH[r0 + 4]; al[mt][2] = XsL[r0 + 4];
                ah[mt][3] = XsH[r8 + 4]; al[mt][3] = XsL[r8 + 4];
            }
            uint32_t bh[4][2], bl[4][2];
            #pragma unroll
            for (int nt = 0; nt < 4; nt++) {
                const int c0 = (cn0 + nt * 8) * SST + kk + tg;
                bh[nt][0] = WsH[c0];     bl[nt][0] = WsL[c0];
                bh[nt][1] = WsH[c0 + 4]; bl[nt][1] = WsL[c0 + 4];
            }
            #pragma unroll
            for (int mt = 0; mt < 2; mt++)
                #pragma unroll
                for (int nt = 0; nt < 4; nt++) {
                    mma_tf32(acc[mt][nt], ah[mt], bh[nt]);
                    mma_tf32(acc[mt][nt], al[mt], bh[nt]);
                    mma_tf32(acc[mt][nt], ah[mt], bl[nt]);
                }
        }
        __syncthreads();
    }

    // epilogue: c0=C[g][2tg], c1=C[g][2tg+1], c2=C[g+8][2tg], c3=C[g+8][2tg+1]
    #pragma unroll
    for (int mt = 0; mt < 2; mt++) {
        #pragma unroll
        for (int nt = 0; nt < 4; nt++) {
            const int row = m0 + wm * 32 + mt * 16 + g;
            const int col = wn * 32 + nt * 8 + 2 * tg;
            float c0 = acc[mt][nt][0], c1 = acc[mt][nt][1];
            float c2 = acc[mt][nt][2], c3 = acc[mt][nt][3];
            if (sel == 3) {
                const float ba0 = b_alpha[col], ba1 = b_alpha[col + 1];
                c0 = sigmoidf_fast(c0 + ba0); c1 = sigmoidf_fast(c1 + ba1);
                c2 = sigmoidf_fast(c2 + ba0); c3 = sigmoidf_fast(c3 + ba1);
            }
            *reinterpret_cast<float2*>(&g_proj[(size_t)row * NCOL + sel * 64 + col])
                = make_float2(c0, c1);
            *reinterpret_cast<float2*>(&g_proj[(size_t)(row + 8) * NCOL + sel * 64 + col])
                = make_float2(c2, c3);
        }
    }
}

// ============================================================================
// Kernel 2: sequential scan with decoupled retrieved-value recurrence (R6).
// ============================================================================
#define DPF 8

struct ScanCtx {
    const float* gp_base;
    float* out;
    uint32_t sbase;
    int b, i, c, loff;
    float dgl, bgl;
};

__device__ __forceinline__ void scan_step(
    const ScanCtx& ctx, int t,
    float2 (&s)[4],
    float2 (&kc)[4], float2 (&kn)[4],
    float2 (&qp)[4], float2 (&qc)[4],
    float v_c, float a_c,
    float& v_n, float& a_n,
    float& r,
    float (&buf)[DPF][NCOL])
{
    {
        int tf = t + DPF - 1;
        if (tf > T_STEPS - 1) tf = T_STEPS - 1;
        int slot = tf & (DPF - 1);
        const float* src = ctx.gp_base + (size_t)tf * BATCH * NCOL + ctx.loff;
        uint32_t sa = ctx.sbase + (uint32_t)(slot * NCOL + ctx.loff) * 4u;
        asm volatile(
            "cp.async.ca.shared.global [%0], [%1], 16;\n\t"
            "cp.async.ca.shared.global [%2], [%3], 16;\n\t"
            :: "r"(sa), "l"(src), "r"(sa + 16u), "l"(src + 4));
        asm volatile("cp.async.commit_group;");
    }
    asm volatile("cp.async.wait_group %0;" :: "n"(DPF - 2));
    __syncwarp();

    const int tn = (t + 1 < T_STEPS) ? (t + 1) : t;
    const float* pn = &buf[tn & (DPF - 1)][0];
    const float* pc = &buf[t & (DPF - 1)][0];
    {
        float4 kv0 = *reinterpret_cast<const float4*>(pn + ctx.c * 8);
        float4 kv1 = *reinterpret_cast<const float4*>(pn + ctx.c * 8 + 4);
        kn[0] = make_float2(kv0.x, kv0.y); kn[1] = make_float2(kv0.z, kv0.w);
        kn[2] = make_float2(kv1.x, kv1.y); kn[3] = make_float2(kv1.z, kv1.w);
        float4 qv0 = *reinterpret_cast<const float4*>(pc + 64 + ctx.c * 8);
        float4 qv1 = *reinterpret_cast<const float4*>(pc + 64 + ctx.c * 8 + 4);
        qc[0] = make_float2(qv0.x, qv0.y); qc[1] = make_float2(qv0.z, qv0.w);
        qc[2] = make_float2(qv1.x, qv1.y); qc[3] = make_float2(qv1.z, qv1.w);
        v_n = pn[128 + ctx.i];
        a_n = pn[192 + ctx.i];
    }

    float2 xa = f2mul(s[0], kn[0]);
    float2 xb = f2mul(s[1], kn[1]);
    float2 oa = f2mul(s[0], qp[0]);
    float2 ob = f2mul(s[1], qp[1]);
    float2 da = f2mul(kc[0], kn[0]);
    float2 db = f2mul(kc[1], kn[1]);
    xa = f2fma(s[2], kn[2], xa);
    xb = f2fma(s[3], kn[3], xb);
    oa = f2fma(s[2], qp[2], oa);
    ob = f2fma(s[3], qp[3], ob);
    da = f2fma(kc[2], kn[2], da);
    db = f2fma(kc[3], kn[3], db);
    xa = f2add(xa, xb);
    oa = f2add(oa, ob);
    da = f2add(da, db);
    float a1 = xa.x + xa.y;
    float oq = oa.x + oa.y;
    float d2 = da.x + da.y;

    a1 += __shfl_xor_sync(0xffffffffu, a1, 1);
    oq += __shfl_xor_sync(0xffffffffu, oq, 1);
    d2 += __shfl_xor_sync(0xffffffffu, d2, 1);
    a1 += __shfl_xor_sync(0xffffffffu, a1, 2);
    oq += __shfl_xor_sync(0xffffffffu, oq, 2);
    d2 += __shfl_xor_sync(0xffffffffu, d2, 2);
    a1 += __shfl_xor_sync(0xffffffffu, a1, 4);
    oq += __shfl_xor_sync(0xffffffffu, oq, 4);
    d2 += __shfl_xor_sync(0xffffffffu, d2, 4);

    float e;
    asm("ex2.approx.f32 %0, %1;" : "=f"(e) : "f"(__fmaf_rn(ctx.dgl, r, ctx.bgl)));
    float gt;
    asm("rcp.approx.f32 %0, %1;" : "=f"(gt) : "f"(1.0f + e));
    const float beta = (1.0f - a_c) * v_c * gt;

    const float2 av = f2dup(a_c);
    const float2 bv = f2dup(beta);
    #pragma unroll
    for (int m = 0; m < 4; m++)
        s[m] = f2fma(av, s[m], f2mul(bv, kc[m]));

    r = __fmaf_rn(a_c, a1, beta * d2);

    if (t > 0 && ctx.c == 0)
        ctx.out[((size_t)(t - 1) * BATCH + ctx.b) * NST + ctx.i] = oq;
}

__global__ void __launch_bounds__(32) scan_kernel(
    const float* __restrict__ S0,
    const float* __restrict__ d_g,
    const float* __restrict__ b_g,
    float* __restrict__ out,
    float* __restrict__ Sfin)
{
    __shared__ __align__(16) float buf[DPF][NCOL];

    const int bx   = blockIdx.x;
    const int b    = bx >> 4;
    const int rg   = bx & 15;
    const int lane = threadIdx.x;
    const int r_   = lane >> 3;
    const int c    = lane & 7;
    const int i    = rg * 4 + r_;

    const float L2E = 1.4426950408889634f;

    ScanCtx ctx;
    ctx.gp_base = &g_proj[(size_t)b * NCOL];
    ctx.out  = out;
    ctx.b = b; ctx.i = i; ctx.c = c;
    ctx.loff = lane * 8;
    ctx.dgl = -d_g[i] * L2E;
    ctx.bgl = -b_g[i] * L2E;
    ctx.sbase = (uint32_t)__cvta_generic_to_shared(&buf[0][0]);

    float2 s[4];
    {
        const float4* sp = reinterpret_cast<const float4*>(&S0[(size_t)(b * NST + i) * NST + c * 8]);
        float4 v0 = sp[0], v1 = sp[1];
        s[0] = make_float2(v0.x, v0.y); s[1] = make_float2(v0.z, v0.w);
        s[2] = make_float2(v1.x, v1.y); s[3] = make_float2(v1.z, v1.w);
    }

    #pragma unroll
    for (int d = 0; d < DPF - 1; d++) {
        const float* src = ctx.gp_base + (size_t)d * BATCH * NCOL + ctx.loff;
        uint32_t sa = ctx.sbase + (uint32_t)(d * NCOL + ctx.loff) * 4u;
        asm volatile(
            "cp.async.ca.shared.global [%0], [%1], 16;\n\t"
            "cp.async.ca.shared.global [%2], [%3], 16;\n\t"
            :: "r"(sa), "l"(src), "r"(sa + 16u), "l"(src + 4));
        asm volatile("cp.async.commit_group;");
    }
    asm volatile("cp.async.wait_group %0;" :: "n"(DPF - 2));
    __syncwarp();

    float2 kA[4], kB[4], qA[4], qB[4];
    float vA, aA, vB, aB;
    {
        const float* p = &buf[0][0];
        float4 kv0 = *reinterpret_cast<const float4*>(p + c * 8);
        float4 kv1 = *reinterpret_cast<const float4*>(p + c * 8 + 4);
        kA[0] = make_float2(kv0.x, kv0.y); kA[1] = make_float2(kv0.z, kv0.w);
        kA[2] = make_float2(kv1.x, kv1.y); kA[3] = make_float2(kv1.z, kv1.w);
        vA = p[128 + i];
        aA = p[192 + i];
    }
    #pragma unroll
    for (int m = 0; m < 4; m++) { qA[m] = make_float2(0.f, 0.f); }

    float r;
    {
        float2 ra = f2mul(s[0], kA[0]);
        float2 rb = f2mul(s[1], kA[1]);
        ra = f2fma(s[2], kA[2], ra);
        rb = f2fma(s[3], kA[3], rb);
        ra = f2add(ra, rb);
        r = ra.x + ra.y;
        r += __shfl_xor_sync(0xffffffffu, r, 1);
        r += __shfl_xor_sync(0xffffffffu, r, 2);
        r += __shfl_xor_sync(0xffffffffu, r, 4);
    }

    for (int t = 0; t < T_STEPS; t += 2) {
        scan_step(ctx, t,     s, kA, kB, qA, qB, vA, aA, vB, aB, r, buf);
        scan_step(ctx, t + 1, s, kB, kA, qB, qA, vB, aB, vA, aA, r, buf);
    }

    {
        float2 oa = f2mul(s[0], qA[0]);
        float2 ob = f2mul(s[1], qA[1]);
        oa = f2fma(s[2], qA[2], oa);
        ob = f2fma(s[3], qA[3], ob);
        oa = f2add(oa, ob);
        float oq = oa.x + oa.y;
        oq += __shfl_xor_sync(0xffffffffu, oq, 1);
        oq += __shfl_xor_sync(0xffffffffu, oq, 2);
        oq += __shfl_xor_sync(0xffffffffu, oq, 4);
        if (c == 0)
            out[((size_t)(T_STEPS - 1) * BATCH + b) * NST + i] = oq;
    }

    float* fp = &Sfin[(size_t)(b * NST + i) * NST + c * 8];
    reinterpret_cast<float4*>(fp)[0] = make_float4(s[0].x, s[0].y, s[1].x, s[1].y);
    reinterpret_cast<float4*>(fp)[1] = make_float4(s[2].x, s[2].y, s[3].x, s[3].y);
}

// ============================================================================
// Kernel 3: apply self-gate y = x * silu(x) = x^2 * sigmoid(x) over out[T,B,N]
// ============================================================================
__global__ void __launch_bounds__(256) gate_kernel(float* __restrict__ out)
{
    int idx = blockIdx.x * 1024 + threadIdx.x * 4;
    float4 v = *reinterpret_cast<float4*>(&out[idx]);
    v.x = v.x * v.x * sigmoidf_fast(v.x);
    v.y = v.y * v.y * sigmoidf_fast(v.y);
    v.z = v.z * v.z * sigmoidf_fast(v.z);
    v.w = v.w * v.w * sigmoidf_fast(v.w);
    *reinterpret_cast<float4*>(&out[idx]) = v;
}

// ============================================================================
extern "C" void kernel_launch(void* const* d_in, const int* in_sizes, int n_in,
                              void* d_out, int out_size) {
    const float* x   = (const float*)d_in[0];
    const float* S0  = (const float*)d_in[1];
    const float* Wk  = (const float*)d_in[2];
    const float* Wv  = (const float*)d_in[3];
    const float* Wq  = (const float*)d_in[4];
    const float* Wa  = (const float*)d_in[5];
    const float* ba  = (const float*)d_in[6];
    const float* dg  = (const float*)d_in[7];
    const float* bg  = (const float*)d_in[8];

    float* out  = (float*)d_out;                         // [T,B,N]
    float* Sfin = out + (size_t)T_STEPS * BATCH * NST;   // [B,N,N]

    dim3 g1(M_ROWS / TBM, 4);
    proj_tc_kernel<<<g1, 256>>>(x, Wk, Wq, Wv, Wa, ba);
    scan_kernel<<<128, 32>>>(S0, dg, bg, out, Sfin);
    gate_kernel<<<(T_STEPS * BATCH * NST) / 1024, 256>>>(out);
}

// round 10
// speedup vs baseline: 1.0120x; 1.0120x over previous
#include <cuda_runtime.h>
#include <cstdint>
#include <cstring>

#define T_STEPS 2048
#define BATCH   8
#define DIMK    1024
#define NST     64
#define M_ROWS  (T_STEPS * BATCH)
#define NCOL    256

// 16 MB scratch: projections, layout [t*BATCH+b][ k(0:64) | q(64:128) | v(128:192) | alpha(192:256) ]
__device__ __align__(16) float g_proj[(size_t)M_ROWS * NCOL];

union F2U { float2 f2; unsigned long long u; };

__device__ __forceinline__ float2 f2fma(float2 a, float2 b, float2 c) {
    F2U ua, ub, uc, ud; ua.f2 = a; ub.f2 = b; uc.f2 = c;
    asm("fma.rn.f32x2 %0, %1, %2, %3;" : "=l"(ud.u) : "l"(ua.u), "l"(ub.u), "l"(uc.u));
    return ud.f2;
}
__device__ __forceinline__ float2 f2mul(float2 a, float2 b) {
    F2U ua, ub, ud; ua.f2 = a; ub.f2 = b;
    asm("mul.rn.f32x2 %0, %1, %2;" : "=l"(ud.u) : "l"(ua.u), "l"(ub.u));
    return ud.f2;
}
__device__ __forceinline__ float2 f2add(float2 a, float2 b) {
    F2U ua, ub, ud; ua.f2 = a; ub.f2 = b;
    asm("add.rn.f32x2 %0, %1, %2;" : "=l"(ud.u) : "l"(ua.u), "l"(ub.u));
    return ud.f2;
}
__device__ __forceinline__ float2 f2dup(float a) {
    F2U ud;
    asm("mov.b64 %0, {%1, %1};" : "=l"(ud.u) : "f"(a));
    return ud.f2;
}
__device__ __forceinline__ float sigmoidf_fast(float x) {
    return __fdividef(1.0f, 1.0f + __expf(-x));
}

// ============================================================================
// tf32 helpers
// ============================================================================
__device__ __forceinline__ uint32_t f2tf(float a) {
    uint32_t r;
    asm("cvt.rna.tf32.f32 %0, %1;" : "=r"(r) : "f"(a));
    return r;
}
__device__ __forceinline__ void tf_split(float a, uint32_t& hi, uint32_t& lo) {
    hi = f2tf(a);
    lo = f2tf(__fsub_rn(a, __uint_as_float(hi)));
}
__device__ __forceinline__ void mma_tf32(float (&d)[4], const uint32_t (&a)[4],
                                         const uint32_t (&b)[2]) {
    asm("mma.sync.aligned.m16n8k8.row.col.f32.tf32.tf32.f32 "
        "{%0,%1,%2,%3},{%4,%5,%6,%7},{%8,%9},{%0,%1,%2,%3};"
        : "+f"(d[0]), "+f"(d[1]), "+f"(d[2]), "+f"(d[3])
        : "r"(a[0]), "r"(a[1]), "r"(a[2]), "r"(a[3]), "r"(b[0]), "r"(b[1]));
}

// ============================================================================
// Kernel 1: projection GEMM, 3xTF32 tensor cores. Hybrid operand staging:
//   X: fp32 in smem, k-PERMUTED so the fragment pair (k, k+4) is adjacent
//      -> one LDS.64 per two fragment elements; hi/lo split in registers.
//   W: pre-split tf32 (hi,lo) interleaved in smem -> one LDS.64 per pair,
//      zero ALU on the B path.
// CTA: 256 thr (8 warps), tile 128m x 64n x 32k. Warp: 32m x 32n.
// ============================================================================
#define TBM 128
#define TBN 64
#define TBK 32
#define XST 40    // u32 per X row (32 + 8 pad): g-rows at banks {0,8,16,24}
#define WST 72    // u32 per W row (64 + 8 pad): same conflict-free structure

__global__ void __launch_bounds__(256, 2) proj_tc_kernel(
    const float* __restrict__ x,
    const float* __restrict__ Wk, const float* __restrict__ Wq,
    const float* __restrict__ Wv, const float* __restrict__ Wa,
    const float* __restrict__ b_alpha)
{
    __shared__ __align__(16) float    Xs[TBM * XST];   // k-permuted fp32
    __shared__ __align__(16) uint32_t Ws[TBN * WST];   // interleaved hi/lo

    const int tid = threadIdx.x;
    const int m0  = blockIdx.x * TBM;
    const int sel = blockIdx.y;
    const float* W = (sel == 0) ? Wk : (sel == 1) ? Wq : (sel == 2) ? Wv : Wa;

    const int warp  = tid >> 5;
    const int lane  = tid & 31;
    const int g     = lane >> 2;       // group 0..7
    const int tg    = lane & 3;        // thread-in-group 0..3
    const int wm    = warp >> 1;       // 0..3  (32 m-rows each)
    const int wn    = warp & 1;        // 0..1  (32 n-cols each)
    const int am0   = wm * 32 + g;
    const int cn0   = wn * 32 + g;

    // loaders: X row = tid>>1 (0..127), k-base (tid&1)*16 (16 floats/thread)
    //          W row = tid>>2 (0..63),  k-base (tid&3)*8  (8 floats/thread)
    const int xrow = tid >> 1;
    const int xkb  = (tid & 1) * 16;
    const int wrw  = tid >> 2;
    const int wkb  = (tid & 3) * 8;

    const float* xp = &x[(size_t)(m0 + xrow) * DIMK + xkb];
    const float* wp = &W[(size_t)wrw * DIMK + wkb];

    float acc[2][4][4];
    #pragma unroll
    for (int mt = 0; mt < 2; mt++)
        #pragma unroll
        for (int nt = 0; nt < 4; nt++)
            #pragma unroll
            for (int j = 0; j < 4; j++) acc[mt][nt][j] = 0.f;

    // register prefetch of first K-tile
    float4 xq[4], wq[2];
    #pragma unroll
    for (int i = 0; i < 4; i++)
        xq[i] = *reinterpret_cast<const float4*>(xp + 4 * i);
    wq[0] = *reinterpret_cast<const float4*>(wp);
    wq[1] = *reinterpret_cast<const float4*>(wp + 4);

    for (int k0 = 0; k0 < DIMK; k0 += TBK) {
        __syncthreads();   // previous tile's compute reads done

        // ---- stage X: pack pairs (k, k+4) adjacent; two 8-blocks ----
        {
            float* xd = &Xs[xrow * XST + xkb];
            const float q0[4] = { xq[0].x, xq[0].y, xq[0].z, xq[0].w };
            const float q1[4] = { xq[1].x, xq[1].y, xq[1].z, xq[1].w };
            const float q2[4] = { xq[2].x, xq[2].y, xq[2].z, xq[2].w };
            const float q3[4] = { xq[3].x, xq[3].y, xq[3].z, xq[3].w };
            #pragma unroll
            for (int j = 0; j < 4; j++) {
                *reinterpret_cast<float2*>(&xd[2 * j])     = make_float2(q0[j], q1[j]);
                *reinterpret_cast<float2*>(&xd[8 + 2 * j]) = make_float2(q2[j], q3[j]);
            }
        }
        // ---- stage W: split to tf32 hi/lo, interleave (hi,lo) pairs ----
        {
            uint32_t h[8], l[8];
            tf_split(wq[0].x, h[0], l[0]); tf_split(wq[0].y, h[1], l[1]);
            tf_split(wq[0].z, h[2], l[2]); tf_split(wq[0].w, h[3], l[3]);
            tf_split(wq[1].x, h[4], l[4]); tf_split(wq[1].y, h[5], l[5]);
            tf_split(wq[1].z, h[6], l[6]); tf_split(wq[1].w, h[7], l[7]);
            uint32_t* wd = &Ws[wrw * WST + wkb * 2];
            *reinterpret_cast<uint4*>(&wd[0])  = make_uint4(h[0], l[0], h[1], l[1]);
            *reinterpret_cast<uint4*>(&wd[4])  = make_uint4(h[2], l[2], h[3], l[3]);
            *reinterpret_cast<uint4*>(&wd[8])  = make_uint4(h[4], l[4], h[5], l[5]);
            *reinterpret_cast<uint4*>(&wd[12]) = make_uint4(h[6], l[6], h[7], l[7]);
        }
        __syncthreads();

        // prefetch next K-tile
        if (k0 + TBK < DIMK) {
            #pragma unroll
            for (int i = 0; i < 4; i++)
                xq[i] = *reinterpret_cast<const float4*>(xp + k0 + TBK + 4 * i);
            wq[0] = *reinterpret_cast<const float4*>(wp + k0 + TBK);
            wq[1] = *reinterpret_cast<const float4*>(wp + k0 + TBK + 4);
        }

        #pragma unroll
        for (int ks = 0; ks < TBK / 8; ks++) {
            const int kk = ks * 8;

            // A fragments: LDS.64 returns (a[k], a[k+4]); split in registers
            uint32_t ah[2][4], al[2][4];
            #pragma unroll
            for (int mt = 0; mt < 2; mt++) {
                float2 p0 = *reinterpret_cast<const float2*>(
                    &Xs[(am0 + mt * 16) * XST + kk + 2 * tg]);
                float2 p8 = *reinterpret_cast<const float2*>(
                    &Xs[(am0 + mt * 16 + 8) * XST + kk + 2 * tg]);
                tf_split(p0.x, ah[mt][0], al[mt][0]);
                tf_split(p8.x, ah[mt][1], al[mt][1]);
                tf_split(p0.y, ah[mt][2], al[mt][2]);
                tf_split(p8.y, ah[mt][3], al[mt][3]);
            }
            // B fragments: pre-split pairs, one LDS.64 each, no ALU
            uint32_t bh[4][2], bl[4][2];
            #pragma unroll
            for (int nt = 0; nt < 4; nt++) {
                const uint32_t* wb = &Ws[(cn0 + nt * 8) * WST];
                uint2 u0 = *reinterpret_cast<const uint2*>(&wb[(kk + tg) * 2]);
                uint2 u1 = *reinterpret_cast<const uint2*>(&wb[(kk + tg + 4) * 2]);
                bh[nt][0] = u0.x; bl[nt][0] = u0.y;
                bh[nt][1] = u1.x; bl[nt][1] = u1.y;
            }
            #pragma unroll
            for (int mt = 0; mt < 2; mt++)
                #pragma unroll
                for (int nt = 0; nt < 4; nt++) {
                    mma_tf32(acc[mt][nt], ah[mt], bh[nt]);
                    mma_tf32(acc[mt][nt], al[mt], bh[nt]);
                    mma_tf32(acc[mt][nt], ah[mt], bl[nt]);
                }
        }
    }

    // epilogue: c0=C[g][2tg], c1=C[g][2tg+1], c2=C[g+8][2tg], c3=C[g+8][2tg+1]
    #pragma unroll
    for (int mt = 0; mt < 2; mt++) {
        #pragma unroll
        for (int nt = 0; nt < 4; nt++) {
            const int row = m0 + wm * 32 + mt * 16 + g;
            const int col = wn * 32 + nt * 8 + 2 * tg;
            float c0 = acc[mt][nt][0], c1 = acc[mt][nt][1];
            float c2 = acc[mt][nt][2], c3 = acc[mt][nt][3];
            if (sel == 3) {
                const float ba0 = b_alpha[col], ba1 = b_alpha[col + 1];
                c0 = sigmoidf_fast(c0 + ba0); c1 = sigmoidf_fast(c1 + ba1);
                c2 = sigmoidf_fast(c2 + ba0); c3 = sigmoidf_fast(c3 + ba1);
            }
            *reinterpret_cast<float2*>(&g_proj[(size_t)row * NCOL + sel * 64 + col])
                = make_float2(c0, c1);
            *reinterpret_cast<float2*>(&g_proj[(size_t)(row + 8) * NCOL + sel * 64 + col])
                = make_float2(c2, c3);
        }
    }
}

// ============================================================================
// Kernel 2: sequential scan with decoupled retrieved-value recurrence (R6/R8).
// ============================================================================
#define DPF 8

struct ScanCtx {
    const float* gp_base;
    float* out;
    uint32_t sbase;
    int b, i, c, loff;
    float dgl, bgl;
};

__device__ __forceinline__ void scan_step(
    const ScanCtx& ctx, int t,
    float2 (&s)[4],
    float2 (&kc)[4], float2 (&kn)[4],
    float2 (&qp)[4], float2 (&qc)[4],
    float v_c, float a_c,
    float& v_n, float& a_n,
    float& r,
    float (&buf)[DPF][NCOL])
{
    {
        int tf = t + DPF - 1;
        if (tf > T_STEPS - 1) tf = T_STEPS - 1;
        int slot = tf & (DPF - 1);
        const float* src = ctx.gp_base + (size_t)tf * BATCH * NCOL + ctx.loff;
        uint32_t sa = ctx.sbase + (uint32_t)(slot * NCOL + ctx.loff) * 4u;
        asm volatile(
            "cp.async.ca.shared.global [%0], [%1], 16;\n\t"
            "cp.async.ca.shared.global [%2], [%3], 16;\n\t"
            :: "r"(sa), "l"(src), "r"(sa + 16u), "l"(src + 4));
        asm volatile("cp.async.commit_group;");
    }
    asm volatile("cp.async.wait_group %0;" :: "n"(DPF - 2));
    __syncwarp();

    const int tn = (t + 1 < T_STEPS) ? (t + 1) : t;
    const float* pn = &buf[tn & (DPF - 1)][0];
    const float* pc = &buf[t & (DPF - 1)][0];
    {
        float4 kv0 = *reinterpret_cast<const float4*>(pn + ctx.c * 8);
        float4 kv1 = *reinterpret_cast<const float4*>(pn + ctx.c * 8 + 4);
        kn[0] = make_float2(kv0.x, kv0.y); kn[1] = make_float2(kv0.z, kv0.w);
        kn[2] = make_float2(kv1.x, kv1.y); kn[3] = make_float2(kv1.z, kv1.w);
        float4 qv0 = *reinterpret_cast<const float4*>(pc + 64 + ctx.c * 8);
        float4 qv1 = *reinterpret_cast<const float4*>(pc + 64 + ctx.c * 8 + 4);
        qc[0] = make_float2(qv0.x, qv0.y); qc[1] = make_float2(qv0.z, qv0.w);
        qc[2] = make_float2(qv1.x, qv1.y); qc[3] = make_float2(qv1.z, qv1.w);
        v_n = pn[128 + ctx.i];
        a_n = pn[192 + ctx.i];
    }

    float2 xa = f2mul(s[0], kn[0]);
    float2 xb = f2mul(s[1], kn[1]);
    float2 oa = f2mul(s[0], qp[0]);
    float2 ob = f2mul(s[1], qp[1]);
    float2 da = f2mul(kc[0], kn[0]);
    float2 db = f2mul(kc[1], kn[1]);
    xa = f2fma(s[2], kn[2], xa);
    xb = f2fma(s[3], kn[3], xb);
    oa = f2fma(s[2], qp[2], oa);
    ob = f2fma(s[3], qp[3], ob);
    da = f2fma(kc[2], kn[2], da);
    db = f2fma(kc[3], kn[3], db);
    xa = f2add(xa, xb);
    oa = f2add(oa, ob);
    da = f2add(da, db);
    float a1 = xa.x + xa.y;
    float oq = oa.x + oa.y;
    float d2 = da.x + da.y;

    a1 += __shfl_xor_sync(0xffffffffu, a1, 1);
    oq += __shfl_xor_sync(0xffffffffu, oq, 1);
    d2 += __shfl_xor_sync(0xffffffffu, d2, 1);
    a1 += __shfl_xor_sync(0xffffffffu, a1, 2);
    oq += __shfl_xor_sync(0xffffffffu, oq, 2);
    d2 += __shfl_xor_sync(0xffffffffu, d2, 2);
    a1 += __shfl_xor_sync(0xffffffffu, a1, 4);
    oq += __shfl_xor_sync(0xffffffffu, oq, 4);
    d2 += __shfl_xor_sync(0xffffffffu, d2, 4);

    float e;
    asm("ex2.approx.f32 %0, %1;" : "=f"(e) : "f"(__fmaf_rn(ctx.dgl, r, ctx.bgl)));
    float gt;
    asm("rcp.approx.f32 %0, %1;" : "=f"(gt) : "f"(1.0f + e));
    const float beta = (1.0f - a_c) * v_c * gt;

    const float2 av = f2dup(a_c);
    const float2 bv = f2dup(beta);
    #pragma unroll
    for (int m = 0; m < 4; m++)
        s[m] = f2fma(av, s[m], f2mul(bv, kc[m]));

    r = __fmaf_rn(a_c, a1, beta * d2);

    if (t > 0 && ctx.c == 0)
        ctx.out[((size_t)(t - 1) * BATCH + ctx.b) * NST + ctx.i] = oq;
}

__global__ void __launch_bounds__(32) scan_kernel(
    const float* __restrict__ S0,
    const float* __restrict__ d_g,
    const float* __restrict__ b_g,
    float* __restrict__ out,
    float* __restrict__ Sfin)
{
    __shared__ __align__(16) float buf[DPF][NCOL];

    const int bx   = blockIdx.x;
    const int b    = bx >> 4;
    const int rg   = bx & 15;
    const int lane = threadIdx.x;
    const int r_   = lane >> 3;
    const int c    = lane & 7;
    const int i    = rg * 4 + r_;

    const float L2E = 1.4426950408889634f;

    ScanCtx ctx;
    ctx.gp_base = &g_proj[(size_t)b * NCOL];
    ctx.out  = out;
    ctx.b = b; ctx.i = i; ctx.c = c;
    ctx.loff = lane * 8;
    ctx.dgl = -d_g[i] * L2E;
    ctx.bgl = -b_g[i] * L2E;
    ctx.sbase = (uint32_t)__cvta_generic_to_shared(&buf[0][0]);

    float2 s[4];
    {
        const float4* sp = reinterpret_cast<const float4*>(&S0[(size_t)(b * NST + i) * NST + c * 8]);
        float4 v0 = sp[0], v1 = sp[1];
        s[0] = make_float2(v0.x, v0.y); s[1] = make_float2(v0.z, v0.w);
        s[2] = make_float2(v1.x, v1.y); s[3] = make_float2(v1.z, v1.w);
    }

    #pragma unroll
    for (int d = 0; d < DPF - 1; d++) {
        const float* src = ctx.gp_base + (size_t)d * BATCH * NCOL + ctx.loff;
        uint32_t sa = ctx.sbase + (uint32_t)(d * NCOL + ctx.loff) * 4u;
        asm volatile(
            "cp.async.ca.shared.global [%0], [%1], 16;\n\t"
            "cp.async.ca.shared.global [%2], [%3], 16;\n\t"
            :: "r"(sa), "l"(src), "r"(sa + 16u), "l"(src + 4));
        asm volatile("cp.async.commit_group;");
    }
    asm volatile("cp.async.wait_group %0;" :: "n"(DPF - 2));
    __syncwarp();

    float2 kA[4], kB[4], qA[4], qB[4];
    float vA, aA, vB, aB;
    {
        const float* p = &buf[0][0];
        float4 kv0 = *reinterpret_cast<const float4*>(p + c * 8);
        float4 kv1 = *reinterpret_cast<const float4*>(p + c * 8 + 4);
        kA[0] = make_float2(kv0.x, kv0.y); kA[1] = make_float2(kv0.z, kv0.w);
        kA[2] = make_float2(kv1.x, kv1.y); kA[3] = make_float2(kv1.z, kv1.w);
        vA = p[128 + i];
        aA = p[192 + i];
    }
    #pragma unroll
    for (int m = 0; m < 4; m++) { qA[m] = make_float2(0.f, 0.f); }

    float r;
    {
        float2 ra = f2mul(s[0], kA[0]);
        float2 rb = f2mul(s[1], kA[1]);
        ra = f2fma(s[2], kA[2], ra);
        rb = f2fma(s[3], kA[3], rb);
        ra = f2add(ra, rb);
        r = ra.x + ra.y;
        r += __shfl_xor_sync(0xffffffffu, r, 1);
        r += __shfl_xor_sync(0xffffffffu, r, 2);
        r += __shfl_xor_sync(0xffffffffu, r, 4);
    }

    for (int t = 0; t < T_STEPS; t += 2) {
        scan_step(ctx, t,     s, kA, kB, qA, qB, vA, aA, vB, aB, r, buf);
        scan_step(ctx, t + 1, s, kB, kA, qB, qA, vB, aB, vA, aA, r, buf);
    }

    {
        float2 oa = f2mul(s[0], qA[0]);
        float2 ob = f2mul(s[1], qA[1]);
        oa = f2fma(s[2], qA[2], oa);
        ob = f2fma(s[3], qA[3], ob);
        oa = f2add(oa, ob);
        float oq = oa.x + oa.y;
        oq += __shfl_xor_sync(0xffffffffu, oq, 1);
        oq += __shfl_xor_sync(0xffffffffu, oq, 2);
        oq += __shfl_xor_sync(0xffffffffu, oq, 4);
        if (c == 0)
            out[((size_t)(T_STEPS - 1) * BATCH + b) * NST + i] = oq;
    }

    float* fp = &Sfin[(size_t)(b * NST + i) * NST + c * 8];
    reinterpret_cast<float4*>(fp)[0] = make_float4(s[0].x, s[0].y, s[1].x, s[1].y);
    reinterpret_cast<float4*>(fp)[1] = make_float4(s[2].x, s[2].y, s[3].x, s[3].y);
}

// ============================================================================
// Kernel 3: apply self-gate y = x * silu(x) = x^2 * sigmoid(x) over out[T,B,N]
// ============================================================================
__global__ void __launch_bounds__(256) gate_kernel(float* __restrict__ out)
{
    int idx = blockIdx.x * 1024 + threadIdx.x * 4;
    float4 v = *reinterpret_cast<float4*>(&out[idx]);
    v.x = v.x * v.x * sigmoidf_fast(v.x);
    v.y = v.y * v.y * sigmoidf_fast(v.y);
    v.z = v.z * v.z * sigmoidf_fast(v.z);
    v.w = v.w * v.w * sigmoidf_fast(v.w);
    *reinterpret_cast<float4*>(&out[idx]) = v;
}

// ============================================================================
extern "C" void kernel_launch(void* const* d_in, const int* in_sizes, int n_in,
                              void* d_out, int out_size) {
    const float* x   = (const float*)d_in[0];
    const float* S0  = (const float*)d_in[1];
    const float* Wk  = (const float*)d_in[2];
    const float* Wv  = (const float*)d_in[3];
    const float* Wq  = (const float*)d_in[4];
    const float* Wa  = (const float*)d_in[5];
    const float* ba  = (const float*)d_in[6];
    const float* dg  = (const float*)d_in[7];
    const float* bg  = (const float*)d_in[8];

    float* out  = (float*)d_out;                         // [T,B,N]
    float* Sfin = out + (size_t)T_STEPS * BATCH * NST;   // [B,N,N]

    dim3 g1(M_ROWS / TBM, 4);
    proj_tc_kernel<<<g1, 256>>>(x, Wk, Wq, Wv, Wa, ba);
    scan_kernel<<<128, 32>>>(S0, dg, bg, out, Sfin);
    gate_kernel<<<(T_STEPS * BATCH * NST) / 1024, 256>>>(out);
}

// round 11
// speedup vs baseline: 1.1363x; 1.1228x over previous
#include <cuda_runtime.h>
#include <cstdint>
#include <cstring>

#define T_STEPS 2048
#define BATCH   8
#define DIMK    1024
#define NST     64
#define M_ROWS  (T_STEPS * BATCH)
#define NCOL    256

#define CHUNK   8
#define NCHUNK  (T_STEPS / CHUNK)   // 256

// 16 MB scratch: projections, layout [t*BATCH+b][ k(0:64) | q(64:128) | v(128:192) | alpha(192:256) ]
__device__ __align__(16) float g_proj[(size_t)M_ROWS * NCOL];
// 1 MB Gram scratch: [b][chunk][ G(64) | H(64) ], G[j][t]=k_j.k_t, H[j][t]=k_j.q_t
__device__ __align__(16) float g_gram[(size_t)BATCH * NCHUNK * 128];

union F2U { float2 f2; unsigned long long u; };

__device__ __forceinline__ float2 f2fma(float2 a, float2 b, float2 c) {
    F2U ua, ub, uc, ud; ua.f2 = a; ub.f2 = b; uc.f2 = c;
    asm("fma.rn.f32x2 %0, %1, %2, %3;" : "=l"(ud.u) : "l"(ua.u), "l"(ub.u), "l"(uc.u));
    return ud.f2;
}
__device__ __forceinline__ float2 f2mul(float2 a, float2 b) {
    F2U ua, ub, ud; ua.f2 = a; ub.f2 = b;
    asm("mul.rn.f32x2 %0, %1, %2;" : "=l"(ud.u) : "l"(ua.u), "l"(ub.u));
    return ud.f2;
}
__device__ __forceinline__ float2 f2dup(float a) {
    F2U ud;
    asm("mov.b64 %0, {%1, %1};" : "=l"(ud.u) : "f"(a));
    return ud.f2;
}
__device__ __forceinline__ float sigmoidf_fast(float x) {
    return __fdividef(1.0f, 1.0f + __expf(-x));
}

// ============================================================================
// tf32 helpers
// ============================================================================
__device__ __forceinline__ uint32_t f2tf(float a) {
    uint32_t r;
    asm("cvt.rna.tf32.f32 %0, %1;" : "=r"(r) : "f"(a));
    return r;
}
__device__ __forceinline__ void tf_split(float a, uint32_t& hi, uint32_t& lo) {
    hi = f2tf(a);
    lo = f2tf(__fsub_rn(a, __uint_as_float(hi)));
}
__device__ __forceinline__ void mma_tf32(float (&d)[4], const uint32_t (&a)[4],
                                         const uint32_t (&b)[2]) {
    asm("mma.sync.aligned.m16n8k8.row.col.f32.tf32.tf32.f32 "
        "{%0,%1,%2,%3},{%4,%5,%6,%7},{%8,%9},{%0,%1,%2,%3};"
        : "+f"(d[0]), "+f"(d[1]), "+f"(d[2]), "+f"(d[3])
        : "r"(a[0]), "r"(a[1]), "r"(a[2]), "r"(a[3]), "r"(b[0]), "r"(b[1]));
}

// ============================================================================
// Kernel 1: projection GEMM on tensor cores, 3xTF32 (R8 version, 169.9us).
// CTA: 256 thr (8 warps), tile 128m x 64n x 32k. Warp: 32m x 32n.
// ============================================================================
#define TBM 128
#define TBN 64
#define TBK 32
#define XS_STRIDE 36
#define WS_STRIDE 36

__global__ void __launch_bounds__(256, 2) proj_tc_kernel(
    const float* __restrict__ x,
    const float* __restrict__ Wk, const float* __restrict__ Wq,
    const float* __restrict__ Wv, const float* __restrict__ Wa,
    const float* __restrict__ b_alpha)
{
    __shared__ __align__(16) float Xs[TBM * XS_STRIDE];   // [m][k]
    __shared__ __align__(16) float Ws[TBN * WS_STRIDE];   // [n][k]

    const int tid = threadIdx.x;
    const int m0  = blockIdx.x * TBM;
    const int sel = blockIdx.y;
    const float* W = (sel == 0) ? Wk : (sel == 1) ? Wq : (sel == 2) ? Wv : Wa;

    const int warp  = tid >> 5;
    const int lane  = tid & 31;
    const int g     = lane >> 2;
    const int tg    = lane & 3;
    const int wm    = warp >> 1;
    const int wn    = warp & 1;
    const int am0   = wm * 32 + g;
    const int cn0   = wn * 32 + g;

    const int lr0 = tid >> 3;
    const int lc0 = (tid & 7) * 4;

    const float* xp = &x[(size_t)(m0 + lr0) * DIMK + lc0];
    const float* wp = &W[(size_t)lr0 * DIMK + lc0];

    float acc[2][4][4];
    #pragma unroll
    for (int mt = 0; mt < 2; mt++)
        #pragma unroll
        for (int nt = 0; nt < 4; nt++)
            #pragma unroll
            for (int j = 0; j < 4; j++) acc[mt][nt][j] = 0.f;

    float4 xr[4], wr[2];
    #pragma unroll
    for (int i = 0; i < 4; i++)
        xr[i] = *reinterpret_cast<const float4*>(xp + (size_t)i * 32 * DIMK);
    #pragma unroll
    for (int i = 0; i < 2; i++)
        wr[i] = *reinterpret_cast<const float4*>(wp + (size_t)i * 32 * DIMK);

    for (int k0 = 0; k0 < DIMK; k0 += TBK) {
        __syncthreads();
        #pragma unroll
        for (int i = 0; i < 4; i++)
            *reinterpret_cast<float4*>(&Xs[(lr0 + 32 * i) * XS_STRIDE + lc0]) = xr[i];
        #pragma unroll
        for (int i = 0; i < 2; i++)
            *reinterpret_cast<float4*>(&Ws[(lr0 + 32 * i) * WS_STRIDE + lc0]) = wr[i];
        __syncthreads();

        if (k0 + TBK < DIMK) {
            #pragma unroll
            for (int i = 0; i < 4; i++)
                xr[i] = *reinterpret_cast<const float4*>(xp + (size_t)i * 32 * DIMK + k0 + TBK);
            #pragma unroll
            for (int i = 0; i < 2; i++)
                wr[i] = *reinterpret_cast<const float4*>(wp + (size_t)i * 32 * DIMK + k0 + TBK);
        }

        #pragma unroll
        for (int ks = 0; ks < TBK / 8; ks++) {
            const int kk = ks * 8;

            uint32_t ah[2][4], al[2][4];
            #pragma unroll
            for (int mt = 0; mt < 2; mt++) {
                const int r0 = (am0 + mt * 16) * XS_STRIDE;
                const int r8 = (am0 + mt * 16 + 8) * XS_STRIDE;
                float a0 = Xs[r0 + kk + tg];
                float a1 = Xs[r8 + kk + tg];
                float a2 = Xs[r0 + kk + tg + 4];
                float a3 = Xs[r8 + kk + tg + 4];
                tf_split(a0, ah[mt][0], al[mt][0]);
                tf_split(a1, ah[mt][1], al[mt][1]);
                tf_split(a2, ah[mt][2], al[mt][2]);
                tf_split(a3, ah[mt][3], al[mt][3]);
            }
            uint32_t bh[4][2], bl[4][2];
            #pragma unroll
            for (int nt = 0; nt < 4; nt++) {
                const int c0 = (cn0 + nt * 8) * WS_STRIDE;
                float b0 = Ws[c0 + kk + tg];
                float b1 = Ws[c0 + kk + tg + 4];
                tf_split(b0, bh[nt][0], bl[nt][0]);
                tf_split(b1, bh[nt][1], bl[nt][1]);
            }
            #pragma unroll
            for (int mt = 0; mt < 2; mt++)
                #pragma unroll
                for (int nt = 0; nt < 4; nt++) {
                    mma_tf32(acc[mt][nt], ah[mt], bh[nt]);
                    mma_tf32(acc[mt][nt], al[mt], bh[nt]);
                    mma_tf32(acc[mt][nt], ah[mt], bl[nt]);
                }
        }
    }

    #pragma unroll
    for (int mt = 0; mt < 2; mt++) {
        #pragma unroll
        for (int nt = 0; nt < 4; nt++) {
            const int row = m0 + wm * 32 + mt * 16 + g;
            const int col = wn * 32 + nt * 8 + 2 * tg;
            float c0 = acc[mt][nt][0], c1 = acc[mt][nt][1];
            float c2 = acc[mt][nt][2], c3 = acc[mt][nt][3];
            if (sel == 3) {
                const float ba0 = b_alpha[col], ba1 = b_alpha[col + 1];
                c0 = sigmoidf_fast(c0 + ba0); c1 = sigmoidf_fast(c1 + ba1);
                c2 = sigmoidf_fast(c2 + ba0); c3 = sigmoidf_fast(c3 + ba1);
            }
            *reinterpret_cast<float2*>(&g_proj[(size_t)row * NCOL + sel * 64 + col])
                = make_float2(c0, c1);
            *reinterpret_cast<float2*>(&g_proj[(size_t)(row + 8) * NCOL + sel * 64 + col])
                = make_float2(c2, c3);
        }
    }
}

// ============================================================================
// Kernel 2: Gram precompute. block = one (chunk, batch): G[j][t]=k_j.k_t,
// H[j][t]=k_j.q_t for the chunk's 8 steps. 128 threads = 128 dots of 64.
// ============================================================================
__global__ void __launch_bounds__(128) gram_kernel()
{
    __shared__ __align__(16) float kq[CHUNK][128];
    const int cb = blockIdx.x;
    const int c  = cb >> 3;
    const int b  = cb & 7;
    const int tid = threadIdx.x;

    // stage k|q (first 128 floats of each step row)
    const int st  = tid >> 4;
    const int off = (tid & 15) * 8;
    const float* src = &g_proj[((size_t)(c * CHUNK + st) * BATCH + b) * NCOL + off];
    *reinterpret_cast<float4*>(&kq[st][off])     = *reinterpret_cast<const float4*>(src);
    *reinterpret_cast<float4*>(&kq[st][off + 4]) = *reinterpret_cast<const float4*>(src + 4);
    __syncthreads();

    const int m = tid >> 6;          // 0 = G, 1 = H
    const int j = (tid >> 3) & 7;
    const int t = tid & 7;
    const float* kj = &kq[j][0];
    const float* xt = &kq[t][m ? 64 : 0];
    float sum = 0.f;
    #pragma unroll
    for (int e = 0; e < 64; e += 4) {
        float4 kv = *reinterpret_cast<const float4*>(kj + e);
        float4 xv = *reinterpret_cast<const float4*>(xt + e);
        sum = __fmaf_rn(kv.x, xv.x, sum);
        sum = __fmaf_rn(kv.y, xv.y, sum);
        sum = __fmaf_rn(kv.z, xv.z, sum);
        sum = __fmaf_rn(kv.w, xv.w, sum);
    }
    g_gram[((size_t)b * NCHUNK + c) * 128 + m * 64 + j * 8 + t] = sum;
}

// ============================================================================
// Kernel 3: chunked scan. Per chunk of 8 steps, with P_t = prod(alpha),
// w_j = beta_j / P_{j+1}:
//   r_t   = P_t    (S0.k_t + sum_{j<t}  w_j G_jt)
//   out_t = P_{t+1}(S0.q_t + sum_{j<=t} w_j H_jt)
//   S_8   = P_8    (S0 + sum_j w_j k_j)
// Only the scalar sigmoid->beta->w chain is serial. G,H from g_gram.
// 128 blocks x 32 threads; 4 rows/warp, 8 lanes/row.
// ============================================================================
#define RS 4
#define SLOT_FLOATS (CHUNK * NCOL + 128)   // 2176

__device__ __forceinline__ void fetch_chunk(
    const float* gp, const float* gram_b, uint32_t sbase, int cf, int slot, int lane)
{
    uint32_t dst = sbase + (uint32_t)(slot * SLOT_FLOATS) * 4u;
    #pragma unroll
    for (int st = 0; st < CHUNK; st++) {
        const float* src = gp + (size_t)(cf * CHUNK + st) * BATCH * NCOL + lane * 8;
        uint32_t d = dst + (uint32_t)(st * NCOL + lane * 8) * 4u;
        asm volatile(
            "cp.async.ca.shared.global [%0], [%1], 16;\n\t"
            "cp.async.ca.shared.global [%2], [%3], 16;\n\t"
            :: "r"(d), "l"(src), "r"(d + 16u), "l"(src + 4));
    }
    const float* gs = gram_b + (size_t)cf * 128 + lane * 4;
    uint32_t d2 = dst + (uint32_t)(CHUNK * NCOL + lane * 4) * 4u;
    asm volatile("cp.async.ca.shared.global [%0], [%1], 16;" :: "r"(d2), "l"(gs));
    asm volatile("cp.async.commit_group;");
}

__global__ void __launch_bounds__(32) scan_kernel(
    const float* __restrict__ S0,
    const float* __restrict__ d_g,
    const float* __restrict__ b_g,
    float* __restrict__ out,     // [T,B,N] raw (gate applied later)
    float* __restrict__ Sfin)    // [B,N,N]
{
    __shared__ __align__(16) float ring[RS][SLOT_FLOATS];

    const int bx   = blockIdx.x;
    const int b    = bx >> 4;
    const int rg   = bx & 15;
    const int lane = threadIdx.x;
    const int r_   = lane >> 3;
    const int c    = lane & 7;
    const int i    = rg * 4 + r_;

    const float L2E = 1.4426950408889634f;
    const float dgl = -d_g[i] * L2E;
    const float bgl = -b_g[i] * L2E;

    const float* gp     = &g_proj[(size_t)b * NCOL];
    const float* gram_b = &g_gram[(size_t)b * NCHUNK * 128];
    const uint32_t sbase = (uint32_t)__cvta_generic_to_shared(&ring[0][0]);

    float2 s[4];
    {
        const float4* sp = reinterpret_cast<const float4*>(&S0[(size_t)(b * NST + i) * NST + c * 8]);
        float4 v0 = sp[0], v1 = sp[1];
        s[0] = make_float2(v0.x, v0.y); s[1] = make_float2(v0.z, v0.w);
        s[2] = make_float2(v1.x, v1.y); s[3] = make_float2(v1.z, v1.w);
    }

    // prologue: fetch chunks 0..2 into slots 0..2
    #pragma unroll
    for (int d = 0; d < RS - 1; d++)
        fetch_chunk(gp, gram_b, sbase, d, d, lane);

    for (int ch = 0; ch < NCHUNK; ch++) {
        {
            int cf = ch + RS - 1;
            if (cf > NCHUNK - 1) cf = NCHUNK - 1;
            fetch_chunk(gp, gram_b, sbase, cf, (ch + RS - 1) & (RS - 1), lane);
        }
        asm volatile("cp.async.wait_group %0;" :: "n"(RS - 2));
        __syncwarp();

        const float* p = &ring[ch & (RS - 1)][0];

        // ---- parallel dots: a[t] = S0.k_t, u[t] = S0.q_t (lane partials) ----
        float a[8], u[8];
        #pragma unroll
        for (int t = 0; t < 8; t++) {
            const float* pt = p + t * NCOL;
            float4 k0 = *reinterpret_cast<const float4*>(pt + c * 8);
            float4 k1 = *reinterpret_cast<const float4*>(pt + c * 8 + 4);
            float4 q0 = *reinterpret_cast<const float4*>(pt + 64 + c * 8);
            float4 q1 = *reinterpret_cast<const float4*>(pt + 64 + c * 8 + 4);
            float2 aa = f2mul(s[0], make_float2(k0.x, k0.y));
            aa = f2fma(s[1], make_float2(k0.z, k0.w), aa);
            aa = f2fma(s[2], make_float2(k1.x, k1.y), aa);
            aa = f2fma(s[3], make_float2(k1.z, k1.w), aa);
            float2 uu = f2mul(s[0], make_float2(q0.x, q0.y));
            uu = f2fma(s[1], make_float2(q0.z, q0.w), uu);
            uu = f2fma(s[2], make_float2(q1.x, q1.y), uu);
            uu = f2fma(s[3], make_float2(q1.z, q1.w), uu);
            a[t] = aa.x + aa.y;
            u[t] = uu.x + uu.y;
        }
        // butterfly reductions over the 8 lanes of this row (a first: on chain)
        #pragma unroll
        for (int t = 0; t < 8; t++) {
            a[t] += __shfl_xor_sync(0xffffffffu, a[t], 1);
            a[t] += __shfl_xor_sync(0xffffffffu, a[t], 2);
            a[t] += __shfl_xor_sync(0xffffffffu, a[t], 4);
        }
        #pragma unroll
        for (int t = 0; t < 8; t++) {
            u[t] += __shfl_xor_sync(0xffffffffu, u[t], 1);
            u[t] += __shfl_xor_sync(0xffffffffu, u[t], 2);
            u[t] += __shfl_xor_sync(0xffffffffu, u[t], 4);
        }

        // ---- per-row scalars: alpha products, reciprocals, (1-a)v ----
        float P[9], Qr[8], cvi[8];
        P[0] = 1.f;
        #pragma unroll
        for (int t = 0; t < 8; t++) {
            float al = p[t * NCOL + 192 + i];
            float vv = p[t * NCOL + 128 + i];
            cvi[t] = (1.f - al) * vv;
            P[t + 1] = P[t] * al;
            asm("rcp.approx.f32 %0, %1;" : "=f"(Qr[t]) : "f"(P[t + 1]));
        }

        // ---- serial scalar chain (8 sigmoid steps) + fan-out into a/u ----
        const float* gG = p + CHUNK * NCOL;
        const float* gH = gG + 64;
        float w[8];
        #pragma unroll
        for (int j = 0; j < 8; j++) {
            float r = P[j] * a[j];
            float e;
            asm("ex2.approx.f32 %0, %1;" : "=f"(e) : "f"(__fmaf_rn(dgl, r, bgl)));
            float gt;
            asm("rcp.approx.f32 %0, %1;" : "=f"(gt) : "f"(1.0f + e));
            float wj = (cvi[j] * gt) * Qr[j];
            w[j] = wj;
            if (j < 7)   // critical-path update first
                a[j + 1] = __fmaf_rn(wj, gG[j * 8 + j + 1], a[j + 1]);
            #pragma unroll
            for (int t2 = j + 2; t2 < 8; t2++)
                a[t2] = __fmaf_rn(wj, gG[j * 8 + t2], a[t2]);
            #pragma unroll
            for (int t2 = j; t2 < 8; t2++)
                u[t2] = __fmaf_rn(wj, gH[j * 8 + t2], u[t2]);
        }

        // ---- outputs: lane c stores step t0+c for row i ----
        out[((size_t)(ch * CHUNK + c) * BATCH + b) * NST + i] = P[c + 1] * u[c];

        // ---- state update: S = P8 * (S0 + sum_j w_j k_j) ----
        #pragma unroll
        for (int j = 0; j < 8; j++) {
            const float* pt = p + j * NCOL + c * 8;
            float4 k0 = *reinterpret_cast<const float4*>(pt);
            float4 k1 = *reinterpret_cast<const float4*>(pt + 4);
            float2 wj2 = f2dup(w[j]);
            s[0] = f2fma(wj2, make_float2(k0.x, k0.y), s[0]);
            s[1] = f2fma(wj2, make_float2(k0.z, k0.w), s[1]);
            s[2] = f2fma(wj2, make_float2(k1.x, k1.y), s[2]);
            s[3] = f2fma(wj2, make_float2(k1.z, k1.w), s[3]);
        }
        {
            float2 P8 = f2dup(P[8]);
            s[0] = f2mul(P8, s[0]); s[1] = f2mul(P8, s[1]);
            s[2] = f2mul(P8, s[2]); s[3] = f2mul(P8, s[3]);
        }
    }

    // write S_final
    float* fp = &Sfin[(size_t)(b * NST + i) * NST + c * 8];
    reinterpret_cast<float4*>(fp)[0] = make_float4(s[0].x, s[0].y, s[1].x, s[1].y);
    reinterpret_cast<float4*>(fp)[1] = make_float4(s[2].x, s[2].y, s[3].x, s[3].y);
}

// ============================================================================
// Kernel 4: apply self-gate y = x * silu(x) = x^2 * sigmoid(x) over out[T,B,N]
// ============================================================================
__global__ void __launch_bounds__(256) gate_kernel(float* __restrict__ out)
{
    int idx = blockIdx.x * 1024 + threadIdx.x * 4;
    float4 v = *reinterpret_cast<float4*>(&out[idx]);
    v.x = v.x * v.x * sigmoidf_fast(v.x);
    v.y = v.y * v.y * sigmoidf_fast(v.y);
    v.z = v.z * v.z * sigmoidf_fast(v.z);
    v.w = v.w * v.w * sigmoidf_fast(v.w);
    *reinterpret_cast<float4*>(&out[idx]) = v;
}

// ============================================================================
extern "C" void kernel_launch(void* const* d_in, const int* in_sizes, int n_in,
                              void* d_out, int out_size) {
    const float* x   = (const float*)d_in[0];
    const float* S0  = (const float*)d_in[1];
    const float* Wk  = (const float*)d_in[2];
    const float* Wv  = (const float*)d_in[3];
    const float* Wq  = (const float*)d_in[4];
    const float* Wa  = (const float*)d_in[5];
    const float* ba  = (const float*)d_in[6];
    const float* dg  = (const float*)d_in[7];
    const float* bg  = (const float*)d_in[8];

    float* out  = (float*)d_out;                         // [T,B,N]
    float* Sfin = out + (size_t)T_STEPS * BATCH * NST;   // [B,N,N]

    dim3 g1(M_ROWS / TBM, 4);
    proj_tc_kernel<<<g1, 256>>>(x, Wk, Wq, Wv, Wa, ba);
    gram_kernel<<<NCHUNK * BATCH, 128>>>();
    scan_kernel<<<128, 32>>>(S0, dg, bg, out, Sfin);
    gate_kernel<<<(T_STEPS * BATCH * NST) / 1024, 256>>>(out);
}